// round 1
// baseline (speedup 1.0000x reference)
#include <cuda_runtime.h>

// QualityPredictorLoss: the reference sorts sims DESCENDING, then sums
// (s[i+1]-s[i]) over adjacent pairs where s[i] < s[i+1]. On a descending-
// sorted array, s[i] >= s[i+1] always holds, so the mask is identically
// false and the loss is exactly +0.0f for ALL inputs. The fastest correct
// kernel therefore just writes zero to the output.
//
// Graph-capturable: single kernel launch, no sync, no allocation.

__global__ void quality_predictor_loss_zero_kernel(float* __restrict__ out, int n) {
    int i = blockIdx.x * blockDim.x + threadIdx.x;
    if (i < n) {
        out[i] = 0.0f;
    }
}

extern "C" void kernel_launch(void* const* d_in, const int* in_sizes, int n_in,
                              void* d_out, int out_size) {
    (void)d_in; (void)in_sizes; (void)n_in;
    float* out = (float*)d_out;
    int n = out_size > 0 ? out_size : 1;
    int threads = 128;
    int blocks = (n + threads - 1) / threads;
    quality_predictor_loss_zero_kernel<<<blocks, threads>>>(out, n);
}